// round 14
// baseline (speedup 1.0000x reference)
#include <cuda_runtime.h>
#include <cuda_bf16.h>

#define B_ 8
#define H_ 12
#define N_ 577
#define HD_ 64
#define BH_ (B_*H_)            // 96
#define NTOK (BH_*N_)          // 55392
#define NPAIR (NTOK/2)         // 27696
#define NNU  332929u           // N*N
#define SLAB (12u*NNU)         // one batch slab: 3,995,148 (divisible by 4)
#define SLAB4 (SLAB/4u)        // 998,787
#define NROWS (12u*577u)       // 6924 rows per slab
#define LOG2E 1.4426950408889634f

#define NB_MAIN ((SLAB4 + 255u)/256u)     // 3902
#define N_CROSS 5193u                      // boundaries 577m, m=1..6923, m%4!=0
#define NB_CROSS ((N_CROSS + 255u)/256u)  // 21

// Per-token coefficients, sign-flipped & pre-scaled by log2(e):
// w'' = c.x*dx^2 + c.y*dx*dy + c.z*dy^2  >= 0,  p = exp2(-w'')
__device__ float4 g_coef4[NTOK];

__device__ __forceinline__ float ex2a(float x){ float r; asm("ex2.approx.f32 %0,%1;" : "=f"(r) : "f"(x)); return r; }
__device__ __forceinline__ float rcpa(float x){ float r; asm("rcp.approx.f32 %0,%1;" : "=f"(r) : "f"(x)); return r; }

// Branch-free gelu (A&S 7.1.26 erf, |err|<=1.5e-7).
__device__ __forceinline__ float gelu_fast(float x)
{
    float z = fabsf(x) * 0.70710678118654752f;
    float t = rcpa(fmaf(0.3275911f, z, 1.0f));
    float poly = fmaf(fmaf(fmaf(fmaf(1.061405429f, t, -1.453152027f), t,
                          1.421413741f), t, -0.284496736f), t, 0.254829592f) * t;
    float e = ex2a(-z * z * LOG2E);
    float erfz = fminf(fmaf(-poly, e, 1.0f), 1.0f);
    float erfs = copysignf(erfz, x);
    return 0.5f * x * (1.0f + erfs);
}

// Branch-free tanh via ex2 (clamp: tanh saturated beyond +-10).
__device__ __forceinline__ float tanh_fast(float s)
{
    s = fminf(fmaxf(s, -10.0f), 10.0f);
    float t2 = ex2a(s * (2.0f * LOG2E));
    return (t2 - 1.0f) * rcpa(t2 + 1.0f);
}

// ---------------------------------------------------------------------------
// Empty kernel: shifts the ncu capture index (-s 5 -c 1) so that launch #5
// is mlp_kernel instead of mask_kernel. Launch order: nop, mlp, nop, mask.
// ---------------------------------------------------------------------------
__global__ void nop_kernel() {}

// ---------------------------------------------------------------------------
// Kernel 1: sigma MLP — quarter-split token pairs (R12/R13 structure,
// UNCHANGED so the captured profile represents the whole 36-40us family).
// ---------------------------------------------------------------------------
__global__ __launch_bounds__(256, 4) void mlp_kernel(
    const float* __restrict__ q,
    const float* __restrict__ W1,
    const float* __restrict__ b1,
    const float* __restrict__ W2,
    const float* __restrict__ b2)
{
    __shared__ float4 w1s[64 * 16];   // [k][j4]
    __shared__ float  b1s[64];
    __shared__ float  w2s[64 * 3];
    __shared__ float  b2s[3];

    const int tid = threadIdx.x;
    for (int idx = tid; idx < 1024; idx += 256) w1s[idx] = ((const float4*)W1)[idx];
    if (tid < 64)  b1s[tid] = b1[tid];
    if (tid < 192) w2s[tid] = W2[tid];
    if (tid < 3)   b2s[tid] = b2[tid];
    __syncthreads();

    int pair = blockIdx.x * 64 + (tid >> 2);
    if (pair >= NPAIR) pair = NPAIR - 1;        // duplicate write, same value: benign
    const int qt = tid & 3;                      // hidden-unit quarter

    const float4* q0 = (const float4*)(q + (size_t)(2 * pair) * HD_);
    const float4* q1 = q0 + 16;

    float h0[16], h1[16];
    #pragma unroll
    for (int j = 0; j < 16; j++) { float b = b1s[qt * 16 + j]; h0[j] = b; h1[j] = b; }

    const int jbase = qt * 4;                    // float4 offset into 16-wide row
    #pragma unroll 2
    for (int k4 = 0; k4 < 16; k4++) {
        float4 a0 = q0[k4];
        float4 a1 = q1[k4];
        float c0k[4] = {a0.x, a0.y, a0.z, a0.w};
        float c1k[4] = {a1.x, a1.y, a1.z, a1.w};
        #pragma unroll
        for (int kk = 0; kk < 4; kk++) {
            const float c0 = c0k[kk];
            const float c1 = c1k[kk];
            const int krow = (k4 * 4 + kk) * 16 + jbase;
            #pragma unroll
            for (int j4 = 0; j4 < 4; j4++) {
                float4 w = w1s[krow + j4];
                h0[4*j4+0] = fmaf(c0, w.x, h0[4*j4+0]);
                h0[4*j4+1] = fmaf(c0, w.y, h0[4*j4+1]);
                h0[4*j4+2] = fmaf(c0, w.z, h0[4*j4+2]);
                h0[4*j4+3] = fmaf(c0, w.w, h0[4*j4+3]);
                h1[4*j4+0] = fmaf(c1, w.x, h1[4*j4+0]);
                h1[4*j4+1] = fmaf(c1, w.y, h1[4*j4+1]);
                h1[4*j4+2] = fmaf(c1, w.z, h1[4*j4+2]);
                h1[4*j4+3] = fmaf(c1, w.w, h1[4*j4+3]);
            }
        }
    }

    float s00 = 0.f, s01 = 0.f, s02 = 0.f;
    float s10 = 0.f, s11 = 0.f, s12 = 0.f;
    #pragma unroll
    for (int j = 0; j < 16; j++) {
        const int jg = (qt * 16 + j) * 3;
        const float w0 = w2s[jg+0], w1w = w2s[jg+1], w2w = w2s[jg+2];
        float g0 = gelu_fast(h0[j]);
        s00 = fmaf(g0, w0, s00); s01 = fmaf(g0, w1w, s01); s02 = fmaf(g0, w2w, s02);
        float g1 = gelu_fast(h1[j]);
        s10 = fmaf(g1, w0, s10); s11 = fmaf(g1, w1w, s11); s12 = fmaf(g1, w2w, s12);
    }
    s00 += __shfl_xor_sync(0xffffffffu, s00, 1);
    s01 += __shfl_xor_sync(0xffffffffu, s01, 1);
    s02 += __shfl_xor_sync(0xffffffffu, s02, 1);
    s10 += __shfl_xor_sync(0xffffffffu, s10, 1);
    s11 += __shfl_xor_sync(0xffffffffu, s11, 1);
    s12 += __shfl_xor_sync(0xffffffffu, s12, 1);
    s00 += __shfl_xor_sync(0xffffffffu, s00, 2);
    s01 += __shfl_xor_sync(0xffffffffu, s01, 2);
    s02 += __shfl_xor_sync(0xffffffffu, s02, 2);
    s10 += __shfl_xor_sync(0xffffffffu, s10, 2);
    s11 += __shfl_xor_sync(0xffffffffu, s11, 2);
    s12 += __shfl_xor_sync(0xffffffffu, s12, 2);

    if (qt == 0) {
        #pragma unroll
        for (int t = 0; t < 2; t++) {
            float s0 = (t ? s10 : s00) + b2s[0];
            float s1 = (t ? s11 : s01) + b2s[1];
            float s2 = (t ? s12 : s02) + b2s[2];
            float sx  = fmaxf(s0, 0.0f) + 1.0f;
            float sy  = fmaxf(s1, 0.0f) + 1.0f;
            float rho = 0.99f * tanh_fast(s2);
            float sxx = sx * sx;
            float syy = sy * sy;
            float sxy = rho * sx * sy;
            float det = sxx * syy - sxy * sxy;   // > 0 always (rho^2 < 0.9801)
            float rdet = 1.0f / det;
            // POSITIVE quadratic form: w'' = -w * log2e
            g_coef4[2 * pair + t] = make_float4( 0.5f * syy * rdet * LOG2E,
                                                -sxy * rdet * LOG2E,
                                                 0.5f * sxx * rdet * LOG2E, 0.f);
        }
    }
}

// ---------------------------------------------------------------------------
// Kernel 2: elementwise mask — R8/R12 optimum, with 32-bit element offsets
// in the batch loop (max index 31.96M < 2^32) to cut 64-bit carry ALU.
// ---------------------------------------------------------------------------
__device__ __forceinline__ float mask_lane(float uu, float xx, float xy, float yy,
                                           float4 c)
{
    float w = fmaf(c.x, xx, fmaf(c.y, xy, c.z * yy));   // >= 0
    float A = ex2a(w) - 1.0f;
    A = fminf(fmaxf(A, 1.0132800e-06f), 999999.0f);
    float r = A * (1.0f - uu) * rcpa(uu);
    float r2 = r * r;
    float r4 = r2 * r2;
    float r10 = r4 * r4 * r2;
    return rcpa(1.0f + r10);
}

__global__ __launch_bounds__(256, 6) void mask_kernel(
    const float* __restrict__ u,
    const float* __restrict__ dists,
    float* __restrict__ out)
{
    const float2* __restrict__ d2 = (const float2*)dists;
    const unsigned bx = blockIdx.x;

    if (bx < NB_MAIN) {
        const unsigned v = bx * 256u + threadIdx.x;
        if (v >= SLAB4) return;
        const unsigned e0 = v * 4u;

        const unsigned rowg = e0 / 577u;          // 0..6923 (= bhl*577 + i)
        const unsigned j    = e0 - rowg * 577u;
        if (j > 573u) return;                     // crossing vector: tail blocks
        const unsigned i    = rowg % 577u;

        const float2* dp = d2 + (size_t)i * 577u + j;
        const float2 d0 = dp[0], d1 = dp[1], dd2 = dp[2], d3 = dp[3];
        const float xx0 = d0.x*d0.x,   xy0 = d0.x*d0.y,   yy0 = d0.y*d0.y;
        const float xx1 = d1.x*d1.x,   xy1 = d1.x*d1.y,   yy1 = d1.y*d1.y;
        const float xx2 = dd2.x*dd2.x, xy2 = dd2.x*dd2.y, yy2 = dd2.y*dd2.y;
        const float xx3 = d3.x*d3.x,   xy3 = d3.x*d3.y,   yy3 = d3.y*d3.y;

        unsigned off = e0;                        // 32-bit element offset
        unsigned ci = rowg;
        #pragma unroll 2
        for (int b = 0; b < 8; b++) {
            const float4 c  = __ldg(&g_coef4[ci]);
            const float4 u4 = __ldcs((const float4*)(u + off));
            float4 res;
            res.x = mask_lane(u4.x, xx0, xy0, yy0, c);
            res.y = mask_lane(u4.y, xx1, xy1, yy1, c);
            res.z = mask_lane(u4.z, xx2, xy2, yy2, c);
            res.w = mask_lane(u4.w, xx3, xy3, yy3, c);
            __stcs((float4*)(out + off), res);
            off += SLAB;
            ci  += NROWS;
        }
    } else {
        // ---- crossing vectors: t -> m (skip m%4==0) -> vector floor(577m/4)
        const unsigned t = (bx - NB_MAIN) * 256u + threadIdx.x;
        if (t >= N_CROSS) return;
        const unsigned m   = t + t / 3u + 1u;     // 1,2,3,5,6,7,9,...
        const unsigned bnd = m * 577u;            // boundary element index
        const unsigned e0  = bnd & ~3u;

        unsigned rowk[4];
        float xxl[4], xyl[4], yyl[4];
        #pragma unroll
        for (int k = 0; k < 4; k++) {
            const unsigned ek = e0 + (unsigned)k;
            const unsigned rg = (ek < bnd) ? (m - 1u) : m;
            rowk[k] = rg;
            const unsigned jk = ek - rg * 577u;
            const unsigned ik = rg % 577u;
            const float2 d = d2[(size_t)ik * 577u + jk];
            xxl[k] = d.x*d.x; xyl[k] = d.x*d.y; yyl[k] = d.y*d.y;
        }

        unsigned off = e0;
        for (int b = 0; b < 8; b++) {
            const float4 u4 = __ldcs((const float4*)(u + off));
            const float ul[4] = {u4.x, u4.y, u4.z, u4.w};
            float rl[4];
            const unsigned cb = (unsigned)b * NROWS;
            #pragma unroll
            for (int k = 0; k < 4; k++) {
                const float4 c = __ldg(&g_coef4[cb + rowk[k]]);
                rl[k] = mask_lane(ul[k], xxl[k], xyl[k], yyl[k], c);
            }
            __stcs((float4*)(out + off), make_float4(rl[0], rl[1], rl[2], rl[3]));
            off += SLAB;
        }
    }
}

extern "C" void kernel_launch(void* const* d_in, const int* in_sizes, int n_in,
                              void* d_out, int out_size)
{
    const float* query = (const float*)d_in[0];
    const float* W1    = (const float*)d_in[1];
    const float* b1    = (const float*)d_in[2];
    const float* W2    = (const float*)d_in[3];
    const float* b2    = (const float*)d_in[4];
    const float* u     = (const float*)d_in[5];
    const float* dists = (const float*)d_in[6];
    float* out = (float*)d_out;

    // Launch order (nop, mlp, nop, mask) puts mlp_kernel at ncu launch #5
    // under both launch-counting conventions (-s 5 -c 1) -> first-ever MLP
    // profile. Costs ~2-4us of empty-launch overhead this round only.
    nop_kernel<<<1, 32>>>();
    mlp_kernel<<<(NPAIR + 63) / 64, 256>>>(query, W1, b1, W2, b2);
    nop_kernel<<<1, 32>>>();
    mask_kernel<<<NB_MAIN + NB_CROSS, 256>>>(u, dists, out);
}

// round 15
// speedup vs baseline: 1.0025x; 1.0025x over previous
#include <cuda_runtime.h>
#include <cuda_bf16.h>

#define B_ 8
#define H_ 12
#define N_ 577
#define HD_ 64
#define BH_ (B_*H_)            // 96
#define NTOK (BH_*N_)          // 55392
#define NPAIR (NTOK/2)         // 27696
#define NNU  332929u           // N*N
#define SLAB (12u*NNU)         // one batch slab: 3,995,148 (divisible by 4)
#define SLAB4 (SLAB/4u)        // 998,787
#define NROWS (12u*577u)       // 6924 rows per slab
#define LOG2E 1.4426950408889634f

#define NB_MAIN ((SLAB4 + 255u)/256u)     // 3902
#define N_CROSS 5193u                      // boundaries 577m, m=1..6923, m%4!=0
#define NB_CROSS ((N_CROSS + 255u)/256u)  // 21

typedef unsigned long long u64;

// Per-token coefficients, sign-flipped & pre-scaled by log2(e):
// w'' = c.x*dx^2 + c.y*dx*dy + c.z*dy^2  >= 0,  p = exp2(-w'')
__device__ float4 g_coef4[NTOK];

__device__ __forceinline__ float ex2a(float x){ float r; asm("ex2.approx.f32 %0,%1;" : "=f"(r) : "f"(x)); return r; }
__device__ __forceinline__ float rcpa(float x){ float r; asm("rcp.approx.f32 %0,%1;" : "=f"(r) : "f"(x)); return r; }

// ---- packed f32x2 helpers (FFMA2: only reachable via PTX fma.rn.f32x2) ----
#define FMA2(o,a,b,c) asm("fma.rn.f32x2 %0,%1,%2,%3;" : "=l"(o) : "l"(a), "l"(b), "l"(c))
__device__ __forceinline__ u64 bcast2(float x){ u64 r; asm("mov.b64 %0,{%1,%1};" : "=l"(r) : "f"(x)); return r; }
__device__ __forceinline__ u64 pack2(float lo, float hi){ u64 r; asm("mov.b64 %0,{%1,%2};" : "=l"(r) : "f"(lo), "f"(hi)); return r; }
__device__ __forceinline__ void unpack2(float& lo, float& hi, u64 v){ asm("mov.b64 {%0,%1},%2;" : "=f"(lo), "=f"(hi) : "l"(v)); }

// Branch-free gelu (A&S 7.1.26 erf, |err|<=1.5e-7).
__device__ __forceinline__ float gelu_fast(float x)
{
    float z = fabsf(x) * 0.70710678118654752f;
    float t = rcpa(fmaf(0.3275911f, z, 1.0f));
    float poly = fmaf(fmaf(fmaf(fmaf(1.061405429f, t, -1.453152027f), t,
                          1.421413741f), t, -0.284496736f), t, 0.254829592f) * t;
    float e = ex2a(-z * z * LOG2E);
    float erfz = fminf(fmaf(-poly, e, 1.0f), 1.0f);
    float erfs = copysignf(erfz, x);
    return 0.5f * x * (1.0f + erfs);
}

// Branch-free tanh via ex2 (clamp: tanh saturated beyond +-10).
__device__ __forceinline__ float tanh_fast(float s)
{
    s = fminf(fmaxf(s, -10.0f), 10.0f);
    float t2 = ex2a(s * (2.0f * LOG2E));
    return (t2 - 1.0f) * rcpa(t2 + 1.0f);
}

// ---------------------------------------------------------------------------
// Kernel 1: sigma MLP — quarter-split token pairs with PACKED f32x2 matmul.
// Each thread: 16 hidden units x 2 tokens, h held as 8 f32x2 pairs per token.
// W1 float4 rows load as two 64-bit lanes (ld.shared.v2.b64, zero pack cost);
// only the q-multiplier needs a mov.b64 broadcast (128/thread vs 1024 FMA
// issues saved). FMA issue count halves: 2048 -> 1024 FFMA2.
// ---------------------------------------------------------------------------
__global__ __launch_bounds__(256, 4) void mlp_kernel(
    const float* __restrict__ q,
    const float* __restrict__ W1,
    const float* __restrict__ b1,
    const float* __restrict__ W2,
    const float* __restrict__ b2)
{
    __shared__ float4 w1s[64 * 16];   // [k][j4], 16B-aligned
    __shared__ float  b1s[64];
    __shared__ float  w2s[64 * 3];
    __shared__ float  b2s[3];

    const int tid = threadIdx.x;
    for (int idx = tid; idx < 1024; idx += 256) w1s[idx] = ((const float4*)W1)[idx];
    if (tid < 64)  b1s[tid] = b1[tid];
    if (tid < 192) w2s[tid] = W2[tid];
    if (tid < 3)   b2s[tid] = b2[tid];
    __syncthreads();

    int pair = blockIdx.x * 64 + (tid >> 2);
    if (pair >= NPAIR) pair = NPAIR - 1;        // duplicate write, same value: benign
    const int qt = tid & 3;                      // hidden-unit quarter

    const float4* q0 = (const float4*)(q + (size_t)(2 * pair) * HD_);
    const float4* q1 = q0 + 16;

    // h as packed pairs: H[p] = hidden units (qt*16 + 2p, qt*16 + 2p + 1)
    u64 H0[8], H1[8];
    #pragma unroll
    for (int p = 0; p < 8; p++) {
        u64 b = pack2(b1s[qt * 16 + 2 * p], b1s[qt * 16 + 2 * p + 1]);
        H0[p] = b; H1[p] = b;
    }

    const unsigned w1s_base = (unsigned)__cvta_generic_to_shared(w1s)
                            + (unsigned)(qt * 4) * 16u;   // jbase offset in bytes

    #pragma unroll 2
    for (int k4 = 0; k4 < 16; k4++) {
        float4 a0 = q0[k4];
        float4 a1 = q1[k4];
        float c0k[4] = {a0.x, a0.y, a0.z, a0.w};
        float c1k[4] = {a1.x, a1.y, a1.z, a1.w};
        #pragma unroll
        for (int kk = 0; kk < 4; kk++) {
            const u64 C0 = bcast2(c0k[kk]);
            const u64 C1 = bcast2(c1k[kk]);
            const unsigned krow_addr = w1s_base + (unsigned)((k4 * 4 + kk) * 16) * 16u;
            #pragma unroll
            for (int j4 = 0; j4 < 4; j4++) {
                u64 wa, wb;   // units 4*j4+{0,1} and 4*j4+{2,3} of this quarter
                asm("ld.shared.v2.b64 {%0,%1},[%2];"
                    : "=l"(wa), "=l"(wb) : "r"(krow_addr + (unsigned)j4 * 16u));
                FMA2(H0[2*j4    ], C0, wa, H0[2*j4    ]);
                FMA2(H0[2*j4 + 1], C0, wb, H0[2*j4 + 1]);
                FMA2(H1[2*j4    ], C1, wa, H1[2*j4    ]);
                FMA2(H1[2*j4 + 1], C1, wb, H1[2*j4 + 1]);
            }
        }
    }

    float s00 = 0.f, s01 = 0.f, s02 = 0.f;
    float s10 = 0.f, s11 = 0.f, s12 = 0.f;
    #pragma unroll
    for (int p = 0; p < 8; p++) {
        float xa, xb;
        unpack2(xa, xb, H0[p]);
        float ya, yb;
        unpack2(ya, yb, H1[p]);
        #pragma unroll
        for (int s = 0; s < 2; s++) {
            const int j = 2 * p + s;
            const int jg = (qt * 16 + j) * 3;
            const float w0 = w2s[jg+0], w1w = w2s[jg+1], w2w = w2s[jg+2];
            float g0 = gelu_fast(s ? xb : xa);
            s00 = fmaf(g0, w0, s00); s01 = fmaf(g0, w1w, s01); s02 = fmaf(g0, w2w, s02);
            float g1 = gelu_fast(s ? yb : ya);
            s10 = fmaf(g1, w0, s10); s11 = fmaf(g1, w1w, s11); s12 = fmaf(g1, w2w, s12);
        }
    }
    // reduce across the 4 quarters of this pair (lanes differ in bits 0..1)
    s00 += __shfl_xor_sync(0xffffffffu, s00, 1);
    s01 += __shfl_xor_sync(0xffffffffu, s01, 1);
    s02 += __shfl_xor_sync(0xffffffffu, s02, 1);
    s10 += __shfl_xor_sync(0xffffffffu, s10, 1);
    s11 += __shfl_xor_sync(0xffffffffu, s11, 1);
    s12 += __shfl_xor_sync(0xffffffffu, s12, 1);
    s00 += __shfl_xor_sync(0xffffffffu, s00, 2);
    s01 += __shfl_xor_sync(0xffffffffu, s01, 2);
    s02 += __shfl_xor_sync(0xffffffffu, s02, 2);
    s10 += __shfl_xor_sync(0xffffffffu, s10, 2);
    s11 += __shfl_xor_sync(0xffffffffu, s11, 2);
    s12 += __shfl_xor_sync(0xffffffffu, s12, 2);

    if (qt == 0) {
        #pragma unroll
        for (int t = 0; t < 2; t++) {
            float s0 = (t ? s10 : s00) + b2s[0];
            float s1 = (t ? s11 : s01) + b2s[1];
            float s2 = (t ? s12 : s02) + b2s[2];
            float sx  = fmaxf(s0, 0.0f) + 1.0f;
            float sy  = fmaxf(s1, 0.0f) + 1.0f;
            float rho = 0.99f * tanh_fast(s2);
            float sxx = sx * sx;
            float syy = sy * sy;
            float sxy = rho * sx * sy;
            float det = sxx * syy - sxy * sxy;   // > 0 always (rho^2 < 0.9801)
            float rdet = 1.0f / det;
            // POSITIVE quadratic form: w'' = -w * log2e
            g_coef4[2 * pair + t] = make_float4( 0.5f * syy * rdet * LOG2E,
                                                -sxy * rdet * LOG2E,
                                                 0.5f * sxx * rdet * LOG2E, 0.f);
        }
    }
}

// ---------------------------------------------------------------------------
// Kernel 2: elementwise mask — R8/R12 optimum + 32-bit offsets (R14).
// Row-max provably 1.0 -> no reduction. Odds form A = exp2(w'')-1
// (Sterbenz-exact), clamped to the f32 image of clip(p, 1e-6, 1-1e-6).
// r = A*(1-u)*rcp(u);  mask = rcp(1 + r^10).
// ---------------------------------------------------------------------------
__device__ __forceinline__ float mask_lane(float uu, float xx, float xy, float yy,
                                           float4 c)
{
    float w = fmaf(c.x, xx, fmaf(c.y, xy, c.z * yy));   // >= 0
    float A = ex2a(w) - 1.0f;
    A = fminf(fmaxf(A, 1.0132800e-06f), 999999.0f);
    float r = A * (1.0f - uu) * rcpa(uu);
    float r2 = r * r;
    float r4 = r2 * r2;
    float r10 = r4 * r4 * r2;
    return rcpa(1.0f + r10);
}

__global__ __launch_bounds__(256, 6) void mask_kernel(
    const float* __restrict__ u,
    const float* __restrict__ dists,
    float* __restrict__ out)
{
    const float2* __restrict__ d2 = (const float2*)dists;
    const unsigned bx = blockIdx.x;

    if (bx < NB_MAIN) {
        const unsigned v = bx * 256u + threadIdx.x;
        if (v >= SLAB4) return;
        const unsigned e0 = v * 4u;

        const unsigned rowg = e0 / 577u;          // 0..6923 (= bhl*577 + i)
        const unsigned j    = e0 - rowg * 577u;
        if (j > 573u) return;                     // crossing vector: tail blocks
        const unsigned i    = rowg % 577u;

        const float2* dp = d2 + (size_t)i * 577u + j;
        const float2 d0 = dp[0], d1 = dp[1], dd2 = dp[2], d3 = dp[3];
        const float xx0 = d0.x*d0.x,   xy0 = d0.x*d0.y,   yy0 = d0.y*d0.y;
        const float xx1 = d1.x*d1.x,   xy1 = d1.x*d1.y,   yy1 = d1.y*d1.y;
        const float xx2 = dd2.x*dd2.x, xy2 = dd2.x*dd2.y, yy2 = dd2.y*dd2.y;
        const float xx3 = d3.x*d3.x,   xy3 = d3.x*d3.y,   yy3 = d3.y*d3.y;

        unsigned off = e0;                        // 32-bit element offset
        unsigned ci = rowg;
        #pragma unroll 2
        for (int b = 0; b < 8; b++) {
            const float4 c  = __ldg(&g_coef4[ci]);
            const float4 u4 = __ldcs((const float4*)(u + off));
            float4 res;
            res.x = mask_lane(u4.x, xx0, xy0, yy0, c);
            res.y = mask_lane(u4.y, xx1, xy1, yy1, c);
            res.z = mask_lane(u4.z, xx2, xy2, yy2, c);
            res.w = mask_lane(u4.w, xx3, xy3, yy3, c);
            __stcs((float4*)(out + off), res);
            off += SLAB;
            ci  += NROWS;
        }
    } else {
        // ---- crossing vectors: t -> m (skip m%4==0) -> vector floor(577m/4)
        const unsigned t = (bx - NB_MAIN) * 256u + threadIdx.x;
        if (t >= N_CROSS) return;
        const unsigned m   = t + t / 3u + 1u;     // 1,2,3,5,6,7,9,...
        const unsigned bnd = m * 577u;            // boundary element index
        const unsigned e0  = bnd & ~3u;

        unsigned rowk[4];
        float xxl[4], xyl[4], yyl[4];
        #pragma unroll
        for (int k = 0; k < 4; k++) {
            const unsigned ek = e0 + (unsigned)k;
            const unsigned rg = (ek < bnd) ? (m - 1u) : m;
            rowk[k] = rg;
            const unsigned jk = ek - rg * 577u;
            const unsigned ik = rg % 577u;
            const float2 d = d2[(size_t)ik * 577u + jk];
            xxl[k] = d.x*d.x; xyl[k] = d.x*d.y; yyl[k] = d.y*d.y;
        }

        unsigned off = e0;
        for (int b = 0; b < 8; b++) {
            const float4 u4 = __ldcs((const float4*)(u + off));
            const float ul[4] = {u4.x, u4.y, u4.z, u4.w};
            float rl[4];
            const unsigned cb = (unsigned)b * NROWS;
            #pragma unroll
            for (int k = 0; k < 4; k++) {
                const float4 c = __ldg(&g_coef4[cb + rowk[k]]);
                rl[k] = mask_lane(ul[k], xxl[k], xyl[k], yyl[k], c);
            }
            __stcs((float4*)(out + off), make_float4(rl[0], rl[1], rl[2], rl[3]));
            off += SLAB;
        }
    }
}

extern "C" void kernel_launch(void* const* d_in, const int* in_sizes, int n_in,
                              void* d_out, int out_size)
{
    const float* query = (const float*)d_in[0];
    const float* W1    = (const float*)d_in[1];
    const float* b1    = (const float*)d_in[2];
    const float* W2    = (const float*)d_in[3];
    const float* b2    = (const float*)d_in[4];
    const float* u     = (const float*)d_in[5];
    const float* dists = (const float*)d_in[6];
    float* out = (float*)d_out;

    mlp_kernel<<<(NPAIR + 63) / 64, 256>>>(query, W1, b1, W2, b2);

    mask_kernel<<<NB_MAIN + NB_CROSS, 256>>>(u, dists, out);
}

// round 16
// speedup vs baseline: 1.0071x; 1.0046x over previous
#include <cuda_runtime.h>
#include <cuda_bf16.h>

#define B_ 8
#define H_ 12
#define N_ 577
#define HD_ 64
#define BH_ (B_*H_)            // 96
#define NTOK (BH_*N_)          // 55392
#define NPAIR (NTOK/2)         // 27696
#define NNU  332929u           // N*N
#define SLAB (12u*NNU)         // one batch slab: 3,995,148 (divisible by 4)
#define SLAB4 (SLAB/4u)        // 998,787
#define NROWS (12u*577u)       // 6924 rows per slab
#define LOG2E 1.4426950408889634f

#define NB_MAIN ((SLAB4 + 255u)/256u)     // 3902
#define N_CROSS 5193u                      // boundaries 577m, m=1..6923, m%4!=0
#define NB_CROSS ((N_CROSS + 255u)/256u)  // 21

#define PAIRS_PB 32                        // pairs per MLP block
#define NB_MLP ((NPAIR + PAIRS_PB - 1)/PAIRS_PB)   // 866

typedef unsigned long long u64;

// Per-token coefficients, sign-flipped & pre-scaled by log2(e):
// w'' = c.x*dx^2 + c.y*dx*dy + c.z*dy^2  >= 0,  p = exp2(-w'')
__device__ float4 g_coef4[NTOK];

__device__ __forceinline__ float ex2a(float x){ float r; asm("ex2.approx.f32 %0,%1;" : "=f"(r) : "f"(x)); return r; }
__device__ __forceinline__ float rcpa(float x){ float r; asm("rcp.approx.f32 %0,%1;" : "=f"(r) : "f"(x)); return r; }

// ---- packed f32x2 helpers (FFMA2: only reachable via PTX fma.rn.f32x2) ----
#define FMA2(o,a,b,c) asm("fma.rn.f32x2 %0,%1,%2,%3;" : "=l"(o) : "l"(a), "l"(b), "l"(c))
__device__ __forceinline__ u64 bcast2(float x){ u64 r; asm("mov.b64 %0,{%1,%1};" : "=l"(r) : "f"(x)); return r; }
__device__ __forceinline__ u64 pack2(float lo, float hi){ u64 r; asm("mov.b64 %0,{%1,%2};" : "=l"(r) : "f"(lo), "f"(hi)); return r; }
__device__ __forceinline__ void unpack2(float& lo, float& hi, u64 v){ asm("mov.b64 {%0,%1},%2;" : "=f"(lo), "=f"(hi) : "l"(v)); }

// Branch-free gelu (A&S 7.1.26 erf, |err|<=1.5e-7).
__device__ __forceinline__ float gelu_fast(float x)
{
    float z = fabsf(x) * 0.70710678118654752f;
    float t = rcpa(fmaf(0.3275911f, z, 1.0f));
    float poly = fmaf(fmaf(fmaf(fmaf(1.061405429f, t, -1.453152027f), t,
                          1.421413741f), t, -0.284496736f), t, 0.254829592f) * t;
    float e = ex2a(-z * z * LOG2E);
    float erfz = fminf(fmaf(-poly, e, 1.0f), 1.0f);
    float erfs = copysignf(erfz, x);
    return 0.5f * x * (1.0f + erfs);
}

// Branch-free tanh via ex2 (clamp: tanh saturated beyond +-10).
__device__ __forceinline__ float tanh_fast(float s)
{
    s = fminf(fmaxf(s, -10.0f), 10.0f);
    float t2 = ex2a(s * (2.0f * LOG2E));
    return (t2 - 1.0f) * rcpa(t2 + 1.0f);
}

// ---------------------------------------------------------------------------
// Kernel 1: sigma MLP — q STAGED THROUGH SHARED MEMORY.
// Each 128-thread block: 32 token-pairs. Prologue cooperatively stages the
// block's 64 tokens of q (16KB) with 8 independent LDG.128/thread (MLP=8,
// DRAM latency amortized), so the FFMA2 mainloop reads q via broadcast LDS —
// no latency-exposed LDG inside the dependent chain.
// smem 33KB -> 6 blocks/SM (24 warps); grid 866 ~ one wave.
// ---------------------------------------------------------------------------
__global__ __launch_bounds__(128, 6) void mlp_kernel(
    const float* __restrict__ q,
    const float* __restrict__ W1,
    const float* __restrict__ b1,
    const float* __restrict__ W2,
    const float* __restrict__ b2)
{
    __shared__ float4 w1s[64 * 16];   // [k][j4] : W1 rows as float4
    __shared__ float4 qs[PAIRS_PB * 2 * 16];   // 64 tokens x 16 float4
    __shared__ float  b1s[64];
    __shared__ float  w2s[64 * 3];
    __shared__ float  b2s[3];

    const int tid = threadIdx.x;

    // stage W1 (8 float4/thread) and q (8 float4/thread, bounds-clamped)
    for (int i = tid; i < 1024; i += 128) w1s[i] = ((const float4*)W1)[i];
    {
        const unsigned base4 = blockIdx.x * (PAIRS_PB * 2u * 16u);
        const unsigned limit = (unsigned)NTOK * 16u;
        #pragma unroll
        for (int r = 0; r < 8; r++) {
            const int i = tid + r * 128;
            const unsigned g = base4 + (unsigned)i;
            qs[i] = (g < limit) ? ((const float4*)q)[g] : make_float4(0.f,0.f,0.f,0.f);
        }
    }
    if (tid < 64)  b1s[tid] = b1[tid];
    for (int i = tid; i < 192; i += 128) w2s[i] = W2[i];
    if (tid < 3)   b2s[tid] = b2[tid];
    __syncthreads();

    // local pair, clamped so the last block's spare threads reuse a valid pair
    int lp = tid >> 2;
    {
        const int maxlp = NPAIR - 1 - blockIdx.x * PAIRS_PB;   // >= 0 always
        if (lp > maxlp) lp = maxlp;
    }
    const int pair = blockIdx.x * PAIRS_PB + lp;
    const int qt = tid & 3;                      // hidden-unit quarter

    const float4* q0 = qs + lp * 32;             // token 2*pair
    const float4* q1 = q0 + 16;                  // token 2*pair+1

    // h as packed pairs: H[p] = hidden units (qt*16 + 2p, qt*16 + 2p + 1)
    u64 H0[8], H1[8];
    #pragma unroll
    for (int p = 0; p < 8; p++) {
        u64 b = pack2(b1s[qt * 16 + 2 * p], b1s[qt * 16 + 2 * p + 1]);
        H0[p] = b; H1[p] = b;
    }

    const unsigned w1s_base = (unsigned)__cvta_generic_to_shared(w1s)
                            + (unsigned)(qt * 4) * 16u;   // quarter offset in bytes

    #pragma unroll 2
    for (int k4 = 0; k4 < 16; k4++) {
        float4 a0 = q0[k4];
        float4 a1 = q1[k4];
        float c0k[4] = {a0.x, a0.y, a0.z, a0.w};
        float c1k[4] = {a1.x, a1.y, a1.z, a1.w};
        #pragma unroll
        for (int kk = 0; kk < 4; kk++) {
            const u64 C0 = bcast2(c0k[kk]);
            const u64 C1 = bcast2(c1k[kk]);
            const unsigned krow_addr = w1s_base + (unsigned)((k4 * 4 + kk) * 16) * 16u;
            #pragma unroll
            for (int j4 = 0; j4 < 4; j4++) {
                u64 wa, wb;   // units 4*j4+{0,1} and 4*j4+{2,3} of this quarter
                asm("ld.shared.v2.b64 {%0,%1},[%2];"
                    : "=l"(wa), "=l"(wb) : "r"(krow_addr + (unsigned)j4 * 16u));
                FMA2(H0[2*j4    ], C0, wa, H0[2*j4    ]);
                FMA2(H0[2*j4 + 1], C0, wb, H0[2*j4 + 1]);
                FMA2(H1[2*j4    ], C1, wa, H1[2*j4    ]);
                FMA2(H1[2*j4 + 1], C1, wb, H1[2*j4 + 1]);
            }
        }
    }

    float s00 = 0.f, s01 = 0.f, s02 = 0.f;
    float s10 = 0.f, s11 = 0.f, s12 = 0.f;
    #pragma unroll
    for (int p = 0; p < 8; p++) {
        float xa, xb;
        unpack2(xa, xb, H0[p]);
        float ya, yb;
        unpack2(ya, yb, H1[p]);
        #pragma unroll
        for (int s = 0; s < 2; s++) {
            const int j = 2 * p + s;
            const int jg = (qt * 16 + j) * 3;
            const float w0 = w2s[jg+0], w1w = w2s[jg+1], w2w = w2s[jg+2];
            float g0 = gelu_fast(s ? xb : xa);
            s00 = fmaf(g0, w0, s00); s01 = fmaf(g0, w1w, s01); s02 = fmaf(g0, w2w, s02);
            float g1 = gelu_fast(s ? yb : ya);
            s10 = fmaf(g1, w0, s10); s11 = fmaf(g1, w1w, s11); s12 = fmaf(g1, w2w, s12);
        }
    }
    // reduce across the 4 quarters of this pair (lanes differ in bits 0..1)
    s00 += __shfl_xor_sync(0xffffffffu, s00, 1);
    s01 += __shfl_xor_sync(0xffffffffu, s01, 1);
    s02 += __shfl_xor_sync(0xffffffffu, s02, 1);
    s10 += __shfl_xor_sync(0xffffffffu, s10, 1);
    s11 += __shfl_xor_sync(0xffffffffu, s11, 1);
    s12 += __shfl_xor_sync(0xffffffffu, s12, 1);
    s00 += __shfl_xor_sync(0xffffffffu, s00, 2);
    s01 += __shfl_xor_sync(0xffffffffu, s01, 2);
    s02 += __shfl_xor_sync(0xffffffffu, s02, 2);
    s10 += __shfl_xor_sync(0xffffffffu, s10, 2);
    s11 += __shfl_xor_sync(0xffffffffu, s11, 2);
    s12 += __shfl_xor_sync(0xffffffffu, s12, 2);

    if (qt == 0) {
        #pragma unroll
        for (int t = 0; t < 2; t++) {
            float s0 = (t ? s10 : s00) + b2s[0];
            float s1 = (t ? s11 : s01) + b2s[1];
            float s2 = (t ? s12 : s02) + b2s[2];
            float sx  = fmaxf(s0, 0.0f) + 1.0f;
            float sy  = fmaxf(s1, 0.0f) + 1.0f;
            float rho = 0.99f * tanh_fast(s2);
            float sxx = sx * sx;
            float syy = sy * sy;
            float sxy = rho * sx * sy;
            float det = sxx * syy - sxy * sxy;   // > 0 always (rho^2 < 0.9801)
            float rdet = 1.0f / det;
            // POSITIVE quadratic form: w'' = -w * log2e
            g_coef4[2 * pair + t] = make_float4( 0.5f * syy * rdet * LOG2E,
                                                -sxy * rdet * LOG2E,
                                                 0.5f * sxx * rdet * LOG2E, 0.f);
        }
    }
}

// ---------------------------------------------------------------------------
// Kernel 2: elementwise mask — R8/R12 optimum + 32-bit offsets (R14, 51.6us).
// Row-max provably 1.0 -> no reduction. Odds form A = exp2(w'')-1
// (Sterbenz-exact), clamped to the f32 image of clip(p, 1e-6, 1-1e-6).
// r = A*(1-u)*rcp(u);  mask = rcp(1 + r^10).
// ---------------------------------------------------------------------------
__device__ __forceinline__ float mask_lane(float uu, float xx, float xy, float yy,
                                           float4 c)
{
    float w = fmaf(c.x, xx, fmaf(c.y, xy, c.z * yy));   // >= 0
    float A = ex2a(w) - 1.0f;
    A = fminf(fmaxf(A, 1.0132800e-06f), 999999.0f);
    float r = A * (1.0f - uu) * rcpa(uu);
    float r2 = r * r;
    float r4 = r2 * r2;
    float r10 = r4 * r4 * r2;
    return rcpa(1.0f + r10);
}

__global__ __launch_bounds__(256, 6) void mask_kernel(
    const float* __restrict__ u,
    const float* __restrict__ dists,
    float* __restrict__ out)
{
    const float2* __restrict__ d2 = (const float2*)dists;
    const unsigned bx = blockIdx.x;

    if (bx < NB_MAIN) {
        const unsigned v = bx * 256u + threadIdx.x;
        if (v >= SLAB4) return;
        const unsigned e0 = v * 4u;

        const unsigned rowg = e0 / 577u;          // 0..6923 (= bhl*577 + i)
        const unsigned j    = e0 - rowg * 577u;
        if (j > 573u) return;                     // crossing vector: tail blocks
        const unsigned i    = rowg % 577u;

        const float2* dp = d2 + (size_t)i * 577u + j;
        const float2 d0 = dp[0], d1 = dp[1], dd2 = dp[2], d3 = dp[3];
        const float xx0 = d0.x*d0.x,   xy0 = d0.x*d0.y,   yy0 = d0.y*d0.y;
        const float xx1 = d1.x*d1.x,   xy1 = d1.x*d1.y,   yy1 = d1.y*d1.y;
        const float xx2 = dd2.x*dd2.x, xy2 = dd2.x*dd2.y, yy2 = dd2.y*dd2.y;
        const float xx3 = d3.x*d3.x,   xy3 = d3.x*d3.y,   yy3 = d3.y*d3.y;

        unsigned off = e0;                        // 32-bit element offset
        unsigned ci = rowg;
        #pragma unroll 2
        for (int b = 0; b < 8; b++) {
            const float4 c  = __ldg(&g_coef4[ci]);
            const float4 u4 = __ldcs((const float4*)(u + off));
            float4 res;
            res.x = mask_lane(u4.x, xx0, xy0, yy0, c);
            res.y = mask_lane(u4.y, xx1, xy1, yy1, c);
            res.z = mask_lane(u4.z, xx2, xy2, yy2, c);
            res.w = mask_lane(u4.w, xx3, xy3, yy3, c);
            __stcs((float4*)(out + off), res);
            off += SLAB;
            ci  += NROWS;
        }
    } else {
        // ---- crossing vectors: t -> m (skip m%4==0) -> vector floor(577m/4)
        const unsigned t = (bx - NB_MAIN) * 256u + threadIdx.x;
        if (t >= N_CROSS) return;
        const unsigned m   = t + t / 3u + 1u;     // 1,2,3,5,6,7,9,...
        const unsigned bnd = m * 577u;            // boundary element index
        const unsigned e0  = bnd & ~3u;

        unsigned rowk[4];
        float xxl[4], xyl[4], yyl[4];
        #pragma unroll
        for (int k = 0; k < 4; k++) {
            const unsigned ek = e0 + (unsigned)k;
            const unsigned rg = (ek < bnd) ? (m - 1u) : m;
            rowk[k] = rg;
            const unsigned jk = ek - rg * 577u;
            const unsigned ik = rg % 577u;
            const float2 d = d2[(size_t)ik * 577u + jk];
            xxl[k] = d.x*d.x; xyl[k] = d.x*d.y; yyl[k] = d.y*d.y;
        }

        unsigned off = e0;
        for (int b = 0; b < 8; b++) {
            const float4 u4 = __ldcs((const float4*)(u + off));
            const float ul[4] = {u4.x, u4.y, u4.z, u4.w};
            float rl[4];
            const unsigned cb = (unsigned)b * NROWS;
            #pragma unroll
            for (int k = 0; k < 4; k++) {
                const float4 c = __ldg(&g_coef4[cb + rowk[k]]);
                rl[k] = mask_lane(ul[k], xxl[k], xyl[k], yyl[k], c);
            }
            __stcs((float4*)(out + off), make_float4(rl[0], rl[1], rl[2], rl[3]));
            off += SLAB;
        }
    }
}

extern "C" void kernel_launch(void* const* d_in, const int* in_sizes, int n_in,
                              void* d_out, int out_size)
{
    const float* query = (const float*)d_in[0];
    const float* W1    = (const float*)d_in[1];
    const float* b1    = (const float*)d_in[2];
    const float* W2    = (const float*)d_in[3];
    const float* b2    = (const float*)d_in[4];
    const float* u     = (const float*)d_in[5];
    const float* dists = (const float*)d_in[6];
    float* out = (float*)d_out;

    mlp_kernel<<<NB_MLP, 128>>>(query, W1, b1, W2, b2);

    mask_kernel<<<NB_MAIN + NB_CROSS, 256>>>(u, dists, out);
}